// round 13
// baseline (speedup 1.0000x reference)
#include <cuda_runtime.h>
#include <cuda_bf16.h>
#include <cstdint>

// Fixed problem shapes
#define BV 4
#define DV 48
#define HV 32
#define WV 88
#define CV 64
#define NXV 200
#define NYV 200
#define HWV (HV * WV)
#define NPB (DV * HWV)                   // 135168 points per batch
#define NPRIME (BV * NPB)                // 540672 points
#define NXY (NXV * NYV)                  // 40000
#define SCRATCH_ELEMS (BV * NXY * CV)    // 10,240,000 floats = 40.96 MB
#define TSZ 64                           // transpose tile: 64 nxy x 64 ch
#define NTILE (NXY / TSZ)                // 625 tiles per batch

// TMA-bulk rezero params
#define CHUNK_BYTES 32768                // 32KB per bulk store
#define NCHUNK ((SCRATCH_ELEMS * 4) / CHUNK_BYTES)   // 1250 exactly

// Point-row scratch: [b][nxy][64ch]; a voxel's 64-channel row is one
// contiguous 256B region. Zero at module load; rezero_kernel restores the
// invariant at the END of every call (valid across graph replays).
__device__ __align__(256) float g_scratch[SCRATCH_ELEMS];

// Per-batch masked scatter: the batch's 10.24MB scratch slice stays
// L2-resident against ~19MB of evict-first streaming reads, so every RED is
// an L2-hit RMW (no DRAM spill).
__global__ void __launch_bounds__(256, 5)
bev_scatter_kernel(const float* __restrict__ x,
                   const float* __restrict__ geom,
                   const float* __restrict__ mask,
                   const float* __restrict__ dxp,
                   const float* __restrict__ bxp,
                   int bn) {
    const int lane = threadIdx.x & 31;
    const int warp = (blockIdx.x * blockDim.x + threadIdx.x) >> 5;
    const int nw   = (gridDim.x * blockDim.x) >> 5;

    const float dx0 = dxp[0], dx1 = dxp[1], dx2 = dxp[2];
    const float b0 = bxp[0] - 0.5f * dx0;
    const float b1 = bxp[1] - 0.5f * dx1;
    const float b2 = bxp[2] - 0.5f * dx2;

    const int half = lane >> 4;          // which of the 2 points per iteration
    const int sl   = lane & 15;          // 4-channel group within the point

    const int pbase = bn * NPB;
    const float* maskb = mask + (bn * 2 + 1) * HWV;
    float* scratchb = g_scratch + (size_t)bn * NXY * CV;

    for (int q0 = warp * 32; q0 < NPB; q0 += nw * 32) {
        // ---- phase 1: all 32 lanes compute one point's voxel id each ----
        const int q = q0 + lane;                 // point within batch
        const int p = pbase + q;                 // global point
        // IEEE fp32 ops match reference; truncation toward zero = astype(int32)
        const float gx = (__ldcs(geom + p * 3 + 0) - b0) / dx0;
        const float gy = (__ldcs(geom + p * 3 + 1) - b1) / dx1;
        const float gz = (__ldcs(geom + p * 3 + 2) - b2) / dx2;
        const int ix = (int)gx;
        const int iy = (int)gy;
        const int iz = (int)gz;

        const int hw = q % HWV;                  // q0 multiple of 32, HWV|NPB

        int vox = -1;
        if ((ix >= 0) & (ix < NXV) &
            (iy >= 0) & (iy < NYV) &
            (iz >= 0) & (iz < 1) &
            (__ldcs(maskb + hw) > 0.5f)) {
            vox = ix * NYV + iy;
        }

        // ---- phase 2: 4 batches x (4 streaming loads, then 4 REDs) ----
        #pragma unroll
        for (int bt = 0; bt < 4; bt++) {
            int    vj[4];
            float4 v[4];
            #pragma unroll
            for (int j = 0; j < 4; j++) {
                const int idx = bt * 8 + 2 * j + half;
                vj[j] = __shfl_sync(0xffffffffu, vox, idx);
                if (vj[j] >= 0) {
                    v[j] = __ldcs(reinterpret_cast<const float4*>(
                        x + (size_t)(pbase + q0 + idx) * CV + 4 * sl));
                }
            }
            #pragma unroll
            for (int j = 0; j < 4; j++) {
                if (vj[j] >= 0) {
                    // 16 lanes -> one contiguous 256B region (2 lines, L2-hit)
                    float* dst = scratchb + (size_t)vj[j] * CV + 4 * sl;
                    asm volatile(
                        "red.global.add.v4.f32 [%0], {%1, %2, %3, %4};"
                        :: "l"(dst), "f"(v[j].x), "f"(v[j].y),
                           "f"(v[j].z), "f"(v[j].w)
                        : "memory");
                }
            }
        }
    }
}

// [b][nxy][64] -> [b][64][nxy] transpose through a 64x64 smem tile.
// Reads contiguous 16KB per block; writes fully coalesced float4 rows.
__global__ void __launch_bounds__(256)
bev_unpack_kernel(float* __restrict__ out) {
    const int tile = blockIdx.x % NTILE;
    const int b    = blockIdx.x / NTILE;
    const int nxy0 = tile * TSZ;
    const int t    = threadIdx.x;

    __shared__ float sm[TSZ][CV + 4];    // pad 4: float4-aligned, skews banks

    const float4* src = reinterpret_cast<const float4*>(
        g_scratch + ((size_t)b * NXY + nxy0) * CV);
    #pragma unroll
    for (int k = 0; k < 4; k++) {
        const int idx = t + k * 256;     // 0..1023
        const int r   = idx >> 4;        // nxy row in tile
        const int c4  = idx & 15;        // float4 column
        *reinterpret_cast<float4*>(&sm[r][4 * c4]) = src[idx];
    }
    __syncthreads();

    const int c = t >> 2;
    const int q = t & 3;
    #pragma unroll
    for (int k = 0; k < 4; k++) {
        const int r0 = 16 * q + 4 * k;   // covers 16 nxy per thread
        float4 o4;
        o4.x = sm[r0 + 0][c];
        o4.y = sm[r0 + 1][c];
        o4.z = sm[r0 + 2][c];
        o4.w = sm[r0 + 3][c];
        *reinterpret_cast<float4*>(
            out + ((size_t)(b * CV + c)) * NXY + nxy0 + r0) = o4;
    }
}

// Re-zero the accumulator via TMA bulk stores: each block zeroes a 32KB smem
// buffer once and fires ONE cp.async.bulk store for its chunk. Offloads the
// 40MB fill to the TMA engine instead of 2.5M STG wavefronts.
__global__ void __launch_bounds__(256)
rezero_kernel() {
    __shared__ __align__(128) float zbuf[CHUNK_BYTES / 4];
    const int t = threadIdx.x;
    float4* zb = reinterpret_cast<float4*>(zbuf);
    #pragma unroll
    for (int k = 0; k < CHUNK_BYTES / 16 / 256; k++) {
        zb[t + k * 256] = make_float4(0.f, 0.f, 0.f, 0.f);
    }
    __syncthreads();
    asm volatile("fence.proxy.async.shared::cta;" ::: "memory");

    if (t == 0) {
        char* dst = reinterpret_cast<char*>(g_scratch)
                    + (size_t)blockIdx.x * CHUNK_BYTES;
        uint32_t saddr;
        asm("{ .reg .u64 tmp; cvta.to.shared.u64 tmp, %1; cvt.u32.u64 %0, tmp; }"
            : "=r"(saddr) : "l"(zbuf));
        asm volatile(
            "cp.async.bulk.global.shared::cta.bulk_group [%0], [%1], %2;"
            :: "l"(dst), "r"(saddr), "r"((uint32_t)CHUNK_BYTES)
            : "memory");
        asm volatile("cp.async.bulk.commit_group;" ::: "memory");
        asm volatile("cp.async.bulk.wait_group 0;" ::: "memory");
    }
}

extern "C" void kernel_launch(void* const* d_in, const int* in_sizes, int n_in,
                              void* d_out, int out_size) {
    const float* x    = (const float*)d_in[0];
    const float* geom = (const float*)d_in[1];
    const float* mask = (const float*)d_in[2];
    const float* dx   = (const float*)d_in[3];
    const float* bx   = (const float*)d_in[4];
    float* out = (float*)d_out;

    // 1) per-batch masked scatter: 10.24MB scratch slice stays L2-resident.
    //    528 blocks x 8 warps = 4224 warps = exactly NPB/32 point-batches.
    for (int b = 0; b < BV; b++) {
        bev_scatter_kernel<<<528, 256>>>(x, geom, mask, dx, bx, b);
    }

    // 2) [nxy][64] -> [64][nxy] tiled transpose, both sides coalesced
    bev_unpack_kernel<<<BV * NTILE, 256>>>(out);

    // 3) restore the zero-invariant via TMA bulk stores (1250 x 32KB)
    rezero_kernel<<<NCHUNK, 256>>>();
}

// round 14
// speedup vs baseline: 1.2876x; 1.2876x over previous
#include <cuda_runtime.h>
#include <cuda_bf16.h>
#include <cstdint>

// Fixed problem shapes
#define BV 4
#define DV 48
#define HV 32
#define WV 88
#define CV 64
#define NXV 200
#define NYV 200
#define HWV (HV * WV)
#define NPRIME (BV * DV * HV * WV)       // 540672 points (divisible by 32)
#define NXY (NXV * NYV)                  // 40000
#define SCRATCH_ELEMS (BV * NXY * CV)    // 10,240,000 floats = 40.96 MB
#define TSZ 64                           // transpose tile: 64 nxy x 64 ch
#define NTILE (NXY / TSZ)                // 625 tiles per batch

// Point-row scratch: [b][nxy][64ch]; a voxel's 64-channel row is one
// contiguous 256B region. Zero at module load; rezero_kernel restores the
// invariant at the END of every call (valid across graph replays) and leaves
// the lines dirty-resident in L2 for the next scatter.
__device__ __align__(256) float g_scratch[SCRATCH_ELEMS];

__global__ void __launch_bounds__(256, 5)
bev_scatter_kernel(const float* __restrict__ x,
                   const float* __restrict__ geom,
                   const float* __restrict__ mask,
                   const float* __restrict__ dxp,
                   const float* __restrict__ bxp) {
    const int lane = threadIdx.x & 31;
    const int warp = (blockIdx.x * blockDim.x + threadIdx.x) >> 5;
    const int nw   = (gridDim.x * blockDim.x) >> 5;

    const float dx0 = dxp[0], dx1 = dxp[1], dx2 = dxp[2];
    const float b0 = bxp[0] - 0.5f * dx0;
    const float b1 = bxp[1] - 0.5f * dx1;
    const float b2 = bxp[2] - 0.5f * dx2;

    const int half = lane >> 4;          // which of the 2 points per iteration
    const int sl   = lane & 15;          // 4-channel group within the point

    // L2 policy: accumulator lines are evict-last; they must win arbitration
    // against the evict-first streaming reads.
    uint64_t pol;
    asm("createpolicy.fractional.L2::evict_last.b64 %0, 1.0;" : "=l"(pol));

    for (int p0 = warp * 32; p0 < NPRIME; p0 += nw * 32) {
        // ---- phase 1: all 32 lanes compute one point's voxel id each ----
        const int p = p0 + lane;
        // Streaming (evict-first) reads; fp32 div + trunc matches reference.
        const float gx = (__ldcs(geom + p * 3 + 0) - b0) / dx0;
        const float gy = (__ldcs(geom + p * 3 + 1) - b1) / dx1;
        const float gz = (__ldcs(geom + p * 3 + 2) - b2) / dx2;
        const int ix = (int)gx;
        const int iy = (int)gy;
        const int iz = (int)gz;

        const int hw = p % HWV;
        const int bn = p / (DV * HWV);   // batch index (N=1)

        int vox = -1;
        if ((ix >= 0) & (ix < NXV) &
            (iy >= 0) & (iy < NYV) &
            (iz >= 0) & (iz < 1) &
            (__ldcs(mask + (bn * 2 + 1) * HWV + hw) > 0.5f)) {
            vox = bn * NXY + ix * NYV + iy;
        }

        // ---- phase 2: 4 batches x (4 streaming loads, then 4 REDs) ----
        #pragma unroll
        for (int bt = 0; bt < 4; bt++) {
            int    vj[4];
            float4 v[4];
            #pragma unroll
            for (int j = 0; j < 4; j++) {
                const int idx = bt * 8 + 2 * j + half;
                vj[j] = __shfl_sync(0xffffffffu, vox, idx);
                if (vj[j] >= 0) {
                    v[j] = __ldcs(reinterpret_cast<const float4*>(
                        x + (size_t)(p0 + idx) * CV + 4 * sl));
                }
            }
            #pragma unroll
            for (int j = 0; j < 4; j++) {
                if (vj[j] >= 0) {
                    // 16 lanes -> one contiguous 256B region; evict-last RMW
                    float* dst = g_scratch + (size_t)vj[j] * CV + 4 * sl;
                    asm volatile(
                        "red.global.L2::cache_hint.add.v4.f32 "
                        "[%0], {%1, %2, %3, %4}, %5;"
                        :: "l"(dst), "f"(v[j].x), "f"(v[j].y),
                           "f"(v[j].z), "f"(v[j].w), "l"(pol)
                        : "memory");
                }
            }
        }
    }
}

// [b][nxy][64] -> [b][64][nxy] transpose through a 64x64 smem tile.
// Reads contiguous 16KB per block; out writes are streaming (write-once) so
// they don't evict the scratch lines rezero is about to re-dirty.
__global__ void __launch_bounds__(256)
bev_unpack_kernel(float* __restrict__ out) {
    const int tile = blockIdx.x % NTILE;
    const int b    = blockIdx.x / NTILE;
    const int nxy0 = tile * TSZ;
    const int t    = threadIdx.x;

    __shared__ float sm[TSZ][CV + 4];    // pad 4: float4-aligned, skews banks

    const float4* src = reinterpret_cast<const float4*>(
        g_scratch + ((size_t)b * NXY + nxy0) * CV);
    #pragma unroll
    for (int k = 0; k < 4; k++) {
        const int idx = t + k * 256;     // 0..1023
        const int r   = idx >> 4;        // nxy row in tile
        const int c4  = idx & 15;        // float4 column
        *reinterpret_cast<float4*>(&sm[r][4 * c4]) = src[idx];
    }
    __syncthreads();

    const int c = t >> 2;
    const int q = t & 3;
    #pragma unroll
    for (int k = 0; k < 4; k++) {
        const int r0 = 16 * q + 4 * k;   // covers 16 nxy per thread
        float4 o4;
        o4.x = sm[r0 + 0][c];
        o4.y = sm[r0 + 1][c];
        o4.z = sm[r0 + 2][c];
        o4.w = sm[r0 + 3][c];
        __stcs(reinterpret_cast<float4*>(
            out + ((size_t)(b * CV + c)) * NXY + nxy0 + r0), o4);
    }
}

// Re-zero the accumulator AFTER consumption (restores the invariant for the
// next call / graph replay). Plain stores: leaves scratch dirty-resident in
// L2, exactly where the next replay's scatter wants it.
__global__ void rezero_kernel() {
    float4* p = reinterpret_cast<float4*>(g_scratch);
    const int n4 = SCRATCH_ELEMS / 4;                 // 2,560,000
    const int stride = gridDim.x * blockDim.x;
    const float4 z = make_float4(0.f, 0.f, 0.f, 0.f);
    for (int i = blockIdx.x * blockDim.x + threadIdx.x; i < n4; i += 4 * stride) {
        p[i] = z;
        if (i + stride     < n4) p[i + stride]     = z;
        if (i + 2 * stride < n4) p[i + 2 * stride] = z;
        if (i + 3 * stride < n4) p[i + 3 * stride] = z;
    }
}

extern "C" void kernel_launch(void* const* d_in, const int* in_sizes, int n_in,
                              void* d_out, int out_size) {
    const float* x    = (const float*)d_in[0];
    const float* geom = (const float*)d_in[1];
    const float* mask = (const float*)d_in[2];
    const float* dx   = (const float*)d_in[3];
    const float* bx   = (const float*)d_in[4];
    float* out = (float*)d_out;

    // 1) masked scatter; evict-last REDs pin the accumulator in L2.
    //    740 = 148 SMs x 5 blocks: exactly one persistent wave.
    bev_scatter_kernel<<<740, 256>>>(x, geom, mask, dx, bx);

    // 2) [nxy][64] -> [64][nxy] tiled transpose, streaming out-writes
    bev_unpack_kernel<<<BV * NTILE, 256>>>(out);

    // 3) restore the zero-invariant (leaves scratch L2-resident)
    rezero_kernel<<<148 * 8, 256>>>();
}